// round 14
// baseline (speedup 1.0000x reference)
#include <cuda_runtime.h>
#include <cuda_fp16.h>

#define NB 128
#define NL 36
#define NV 36
#define ND 512
#define NKV 112
#define NQ 36
#define NH 512
#define G3 108
#define CKDIM 812   // D + KD
#define XDIM 624    // D + KV
#define HP 516      // padded pitch (conflict-free LDS.128)
#define KNP 116     // padded pitch for knowledge rows

typedef unsigned long long u64;

__device__ __forceinline__ void ffma2(u64& d, u64 a, u64 b) {
    asm("fma.rn.f32x2 %0, %1, %2, %0;" : "+l"(d) : "l"(a), "l"(b));
}
__device__ __forceinline__ float hsum2(u64 v) {
    float lo, hi;
    asm("mov.b64 {%0,%1}, %2;" : "=f"(lo), "=f"(hi) : "l"(v));
    return lo + hi;
}

// ---------------- scratch ----------------
__device__ float g_csum[NB * NV * ND];
__device__ float g_csumWT[NB * G3 * NQ];  // [b][o][v]
__device__ float g_gk[NB * NL * G3];
__device__ float g_w[NB * ND];
__device__ uint2 g_ctxh[NB * NL * NV * (ND / 4)];  // fp16x4-packed context copy (170MB)

// ---------------- gk = knowledge @ Wih_k^T + bih : one block per batch ----------------
__global__ __launch_bounds__(512) void k_gk(const float* __restrict__ kn,
                                            const float* __restrict__ Wih,
                                            const float* __restrict__ bih) {
    extern __shared__ float s[];
    float* wS  = s;                 // G3 x KNP
    float* knS = s + G3 * KNP;      // NL x KNP
    int b = blockIdx.x, t = threadIdx.x;
    for (int i = t; i < G3 * NKV; i += 512) {
        int o = i / NKV, c = i - o * NKV;
        wS[o * KNP + c] = Wih[o * XDIM + ND + c];
    }
    const float* knb = kn + (size_t)b * NL * NKV;
    for (int i = t; i < NL * NKV; i += 512) {
        int l = i / NKV, c = i - l * NKV;
        knS[l * KNP + c] = knb[i];
    }
    __syncthreads();
    for (int idx = t; idx < NL * G3; idx += 512) {
        int l = idx / G3, o = idx - l * G3;
        const ulonglong2* kr = (const ulonglong2*)(knS + l * KNP);
        const ulonglong2* wr = (const ulonglong2*)(wS + o * KNP);
        u64 a0 = 0, a1 = 0;
        #pragma unroll 7
        for (int c = 0; c < 28; c += 2) {
            ulonglong2 u0 = kr[c], w0 = wr[c], u1 = kr[c + 1], w1 = wr[c + 1];
            ffma2(a0, u0.x, w0.x); ffma2(a0, u0.y, w0.y);
            ffma2(a1, u1.x, w1.x); ffma2(a1, u1.y, w1.y);
        }
        g_gk[(size_t)(b * NL + l) * G3 + o] = bih[o] + hsum2(a0) + hsum2(a1);
    }
}

// ---------------- projection vector w (per-iteration) ----------------
__global__ void k_w(const float* __restrict__ slots, int bstride,
                    const float* __restrict__ lng, const float* __restrict__ lnb,
                    const float* __restrict__ Wq, const float* __restrict__ Wk) {
    int b = blockIdx.x;
    int t = threadIdx.x, lane = t & 31, wid = t >> 5;
    __shared__ float lnS[NQ * NQ];
    __shared__ float lnsum[NQ];
    __shared__ float qsum[NQ];
    const float* sp = slots + (size_t)bstride * b;
    for (int i = wid; i < NQ; i += 8) {
        float v1 = (lane < NQ)      ? sp[i * NQ + lane]      : 0.f;
        float v2 = (lane < NQ - 32) ? sp[i * NQ + lane + 32] : 0.f;
        float s = v1 + v2;
        for (int o = 16; o; o >>= 1) s += __shfl_xor_sync(~0u, s, o);
        float mu = s * (1.f / 36.f);
        float d1 = (lane < NQ) ? (v1 - mu) : 0.f;
        float d2 = (lane < NQ - 32) ? (v2 - mu) : 0.f;
        float vv = d1 * d1 + d2 * d2;
        for (int o = 16; o; o >>= 1) vv += __shfl_xor_sync(~0u, vv, o);
        float inv = rsqrtf(vv * (1.f / 36.f) + 1e-5f);
        if (lane < NQ)      lnS[i * NQ + lane]      = d1 * inv * lng[lane] + lnb[lane];
        if (lane < NQ - 32) lnS[i * NQ + lane + 32] = d2 * inv * lng[lane + 32] + lnb[lane + 32];
    }
    __syncthreads();
    if (t < NQ) {
        float s = 0.f;
        for (int i = 0; i < NQ; i++) s += lnS[i * NQ + t];
        lnsum[t] = s;
    }
    __syncthreads();
    if (t < NQ) {
        float s = 0.f;
        #pragma unroll 4
        for (int e = 0; e < NQ; e++) s += lnsum[e] * Wq[t * NQ + e];
        qsum[t] = s;
    }
    __syncthreads();
    for (int c = t; c < ND; c += blockDim.x) {
        float s = 0.f;
        #pragma unroll 4
        for (int d = 0; d < NQ; d++) s += qsum[d] * Wk[d * CKDIM + c];
        g_w[b * ND + c] = s * (1.f / 6.f);
    }
}

// ---------------- fused iter-0: csum + dots + fp16 context copy ----------------
__global__ __launch_bounds__(128) void k_cd(const float* __restrict__ ctx,
                                            float* __restrict__ dots0) {
    int v = blockIdx.x, b = blockIdx.y;
    int t = threadIdx.x, lane = t & 31, w = t >> 5;
    __shared__ float ppS[18 * 129];
    const float4* wb = (const float4*)(g_w + b * ND);
    float4 w4 = wb[t];
    float4 acc = {0.f, 0.f, 0.f, 0.f};
    size_t row0 = (size_t)b * NL * NV + v;
    const float4* base = (const float4*)ctx + row0 * (ND / 4) + t;
    #pragma unroll 1
    for (int half = 0; half < 2; half++) {
        #pragma unroll 3
        for (int li = 0; li < 18; li++) {
            int l = half * 18 + li;
            float4 c = base[(size_t)l * NV * (ND / 4)];
            acc.x += c.x; acc.y += c.y; acc.z += c.z; acc.w += c.w;
            ppS[li * 129 + t] = c.x * w4.x + c.y * w4.y + c.z * w4.z + c.w * w4.w;
            __half2 h0 = __floats2half2_rn(c.x, c.y);
            __half2 h1 = __floats2half2_rn(c.z, c.w);
            uint2 u;
            u.x = *(unsigned*)&h0;
            u.y = *(unsigned*)&h1;
            g_ctxh[(row0 + (size_t)l * NV) * (ND / 4) + t] = u;
        }
        __syncthreads();
        for (int li = w; li < 18; li += 4) {
            float s = ppS[li * 129 + lane] + ppS[li * 129 + lane + 32]
                    + ppS[li * 129 + lane + 64] + ppS[li * 129 + lane + 96];
            for (int o = 16; o; o >>= 1) s += __shfl_xor_sync(~0u, s, o);
            if (lane == 0) dots0[(b * NL + half * 18 + li) * NV + v] = s;
        }
        __syncthreads();
    }
    ((float4*)g_csum)[(b * NV + v) * (ND / 4) + t] = acc;
}

// ---------------- projection: csumWT[b] = Wihu @ csum[b]^T ----------------
// grid (NB, 2); 2 worker-groups of 162, each a 3(o)x4(v) tile over HALF of K.
// 384 threads = 12 warps for latency hiding; identical total LDS traffic.
__global__ __launch_bounds__(384) void k_projW(const float* __restrict__ Wih) {
    int b = blockIdx.x, part = blockIdx.y;
    int t = threadIdx.x;
    extern __shared__ float sm[];
    float* csS   = sm;                    // 36 rows, pitch 516
    float* wkS   = sm + NV * 516;         // 54 rows, pitch 516
    float* partS = sm + (NV + 54) * 516;  // 162 x 12 partials
    const float4* src = (const float4*)(g_csum + (size_t)b * NV * ND);
    for (int i = t; i < NV * 128; i += 384) {
        int v = i >> 7, c4 = i & 127;
        ((float4*)(csS + v * 516))[c4] = src[i];
    }
    int o0 = part * 54;
    for (int i = t; i < 54 * 128; i += 384) {
        int od = i >> 7, c4 = i & 127;
        ((float4*)(wkS + od * 516))[c4] = ((const float4*)(Wih + (size_t)(o0 + od) * XDIM))[c4];
    }
    __syncthreads();
    u64 acc[12];
    int id = -1;
    if (t < 324) {
        int g = t / 162;
        id = t - g * 162;
        int ot = id / 9, vt = id - (id / 9) * 9;   // ot 0..17, vt 0..8
        int k0 = g * 64;
        const ulonglong2* w0 = (const ulonglong2*)(wkS + ot * 516) + k0;
        const ulonglong2* w1 = (const ulonglong2*)(wkS + (ot + 18) * 516) + k0;
        const ulonglong2* w2 = (const ulonglong2*)(wkS + (ot + 36) * 516) + k0;
        const ulonglong2* c0 = (const ulonglong2*)(csS + vt * 516) + k0;
        const ulonglong2* c1 = (const ulonglong2*)(csS + (vt + 9) * 516) + k0;
        const ulonglong2* c2 = (const ulonglong2*)(csS + (vt + 18) * 516) + k0;
        const ulonglong2* c3 = (const ulonglong2*)(csS + (vt + 27) * 516) + k0;
        #pragma unroll
        for (int i = 0; i < 12; i++) acc[i] = 0;
        #pragma unroll 4
        for (int c = 0; c < 64; c++) {
            ulonglong2 a0 = w0[c], a1 = w1[c], a2 = w2[c];
            ulonglong2 b0 = c0[c], b1 = c1[c], b2 = c2[c], b3 = c3[c];
            ffma2(acc[0],  b0.x, a0.x); ffma2(acc[0],  b0.y, a0.y);
            ffma2(acc[1],  b1.x, a0.x); ffma2(acc[1],  b1.y, a0.y);
            ffma2(acc[2],  b2.x, a0.x); ffma2(acc[2],  b2.y, a0.y);
            ffma2(acc[3],  b3.x, a0.x); ffma2(acc[3],  b3.y, a0.y);
            ffma2(acc[4],  b0.x, a1.x); ffma2(acc[4],  b0.y, a1.y);
            ffma2(acc[5],  b1.x, a1.x); ffma2(acc[5],  b1.y, a1.y);
            ffma2(acc[6],  b2.x, a1.x); ffma2(acc[6],  b2.y, a1.y);
            ffma2(acc[7],  b3.x, a1.x); ffma2(acc[7],  b3.y, a1.y);
            ffma2(acc[8],  b0.x, a2.x); ffma2(acc[8],  b0.y, a2.y);
            ffma2(acc[9],  b1.x, a2.x); ffma2(acc[9],  b1.y, a2.y);
            ffma2(acc[10], b2.x, a2.x); ffma2(acc[10], b2.y, a2.y);
            ffma2(acc[11], b3.x, a2.x); ffma2(acc[11], b3.y, a2.y);
        }
        if (t >= 162) {
            #pragma unroll
            for (int i = 0; i < 12; i++) partS[id * 12 + i] = hsum2(acc[i]);
        }
    }
    __syncthreads();
    if (t < 162) {
        int ot = id / 9, vt = id - (id / 9) * 9;
        float* outb = g_csumWT + b * G3 * NQ;
        #pragma unroll
        for (int oi = 0; oi < 3; oi++)
            #pragma unroll
            for (int vi = 0; vi < 4; vi++)
                outb[(o0 + ot + oi * 18) * NQ + (vt + vi * 9)] =
                    hsum2(acc[oi * 4 + vi]) + partS[id * 12 + oi * 4 + vi];
    }
}

// ---------------- iters 1,2: streaming dots + softmax over fp16 context ----------------
__global__ __launch_bounds__(128) void k_d2h(float* __restrict__ attnT) {
    int l = blockIdx.x, b = blockIdx.y;
    int t = threadIdx.x, lane = t & 31, w = t >> 5;
    __shared__ float ppS[18 * 129];
    __shared__ float dotsS[NV];
    const float4* wb = (const float4*)(g_w + b * ND);
    float4 w4 = wb[t];
    const uint2* base = g_ctxh + ((size_t)(b * NL + l) * NV) * (ND / 4) + t;
    #pragma unroll 1
    for (int half = 0; half < 2; half++) {
        #pragma unroll 3
        for (int vi = 0; vi < 18; vi++) {
            int v = half * 18 + vi;
            uint2 u = base[v * (ND / 4)];
            float2 f0 = __half22float2(*(__half2*)&u.x);
            float2 f1 = __half22float2(*(__half2*)&u.y);
            ppS[vi * 129 + t] = f0.x * w4.x + f0.y * w4.y + f1.x * w4.z + f1.y * w4.w;
        }
        __syncthreads();
        for (int vi = w; vi < 18; vi += 4) {
            float s = ppS[vi * 129 + lane] + ppS[vi * 129 + lane + 32]
                    + ppS[vi * 129 + lane + 64] + ppS[vi * 129 + lane + 96];
            for (int o = 16; o; o >>= 1) s += __shfl_xor_sync(~0u, s, o);
            if (lane == 0) dotsS[half * 18 + vi] = s;
        }
        __syncthreads();
    }
    if (w == 0) {
        float x1 = dotsS[lane];
        float x2 = (lane < 4) ? dotsS[lane + 32] : -1e30f;
        float m = fmaxf(x1, x2);
        for (int o = 16; o; o >>= 1) m = fmaxf(m, __shfl_xor_sync(~0u, m, o));
        float e1 = expf(x1 - m);
        float e2 = (lane < 4) ? expf(x2 - m) : 0.f;
        float s = e1 + e2;
        for (int o = 16; o; o >>= 1) s += __shfl_xor_sync(~0u, s, o);
        float inv = 1.f / s;
        float* arow = attnT + (b * NL + l) * NV;
        arow[lane] = e1 * inv;
        if (lane < 4) arow[lane + 32] = e2 * inv;
    }
}

// ---------------- fused GRU + LN + MLP, split per (b, i-half). 53KB smem. ----------------
#define KG2_FLOATS 13176
__global__ __launch_bounds__(512) void k_g(const float* __restrict__ attnT,
                                           const float* __restrict__ slots_prev, int bstride,
                                           const float* __restrict__ Whh,
                                           const float* __restrict__ bhh,
                                           const float* __restrict__ lnfg, const float* __restrict__ lnfb,
                                           const float* __restrict__ W1, const float* __restrict__ b1,
                                           const float* __restrict__ W2, const float* __restrict__ b2,
                                           int do_sm,
                                           float* __restrict__ attnT_out,
                                           float* __restrict__ slots_out) {
    extern __shared__ float sm[];
    float* attnS = sm;            // -> gnewS
    float* hpS   = sm + 648;      // -> ffS
    float* sumS  = sm + 1296;
    float* gxnS  = sm + 2592;
    float* ghnS  = sm + 3240;
    float* hidS  = sm + 3888;
    float* gnewS = attnS;
    float* ffS   = hpS;
    int b = blockIdx.x, half = blockIdx.y;
    int t = threadIdx.x, lane = t & 31, wp = t >> 5;
    int rbase = b * 1296 + half * 648;

    // hoisted independent W1-row prefetch (overlaps smem-fill latency)
    ulonglong2 w1p[9];
    {
        const ulonglong2* wr = (const ulonglong2*)(W1 + t * NQ);
        #pragma unroll
        for (int c = 0; c < 9; c++) w1p[c] = wr[c];
    }
    float bb1 = b1[t];

    for (int i = t; i < 648; i += 512) {
        attnS[i] = attnT[rbase + i];
        hpS[i] = slots_prev[(size_t)bstride * b + half * 648 + i];
    }
    __syncthreads();

    if (do_sm) {
        for (int i = wp; i < 18; i += 16) {
            float x1 = (lane < NV) ? attnS[i * NV + lane] : -1e30f;
            float x2 = (lane < 4)  ? attnS[i * NV + lane + 32] : -1e30f;
            float m = fmaxf(x1, x2);
            for (int o = 16; o; o >>= 1) m = fmaxf(m, __shfl_xor_sync(~0u, m, o));
            float e1 = (lane < NV) ? expf(x1 - m) : 0.f;
            float e2 = (lane < 4)  ? expf(x2 - m) : 0.f;
            float s = e1 + e2;
            for (int o = 16; o; o >>= 1) s += __shfl_xor_sync(~0u, s, o);
            float inv = 1.f / s;
            float* arow = attnT_out + rbase + i * NV;
            if (lane < NV) { attnS[i * NV + lane] = e1 * inv; arow[lane] = e1 * inv; }
            if (lane < 4)  { attnS[i * NV + lane + 32] = e2 * inv; arow[lane + 32] = e2 * inv; }
        }
        __syncthreads();
    }

    // (a) gates: 2x2 tiles (i2,i2+9) x (o2,o2+54), 486 tasks
    if (t < 486) {
        int i2 = t / 54, o2 = t - i2 * 54;
        const ulonglong2* ar0 = (const ulonglong2*)(attnS + i2 * NQ);
        const ulonglong2* ar1 = (const ulonglong2*)(attnS + (i2 + 9) * NQ);
        const ulonglong2* hr0 = (const ulonglong2*)(hpS + i2 * NQ);
        const ulonglong2* hr1 = (const ulonglong2*)(hpS + (i2 + 9) * NQ);
        const ulonglong2* cw0 = (const ulonglong2*)(g_csumWT + b * G3 * NQ + o2 * NQ);
        const ulonglong2* cw1 = (const ulonglong2*)(g_csumWT + b * G3 * NQ + (o2 + 54) * NQ);
        const ulonglong2* wh0 = (const ulonglong2*)(Whh + o2 * NQ);
        const ulonglong2* wh1 = (const ulonglong2*)(Whh + (o2 + 54) * NQ);
        u64 x00 = 0, x01 = 0, x10 = 0, x11 = 0;
        u64 h00 = 0, h01 = 0, h10 = 0, h11 = 0;
        #pragma unroll
        for (int j = 0; j < 9; j++) {
            ulonglong2 a0 = ar0[j], a1 = ar1[j], c0 = cw0[j], c1 = cw1[j];
            ffma2(x00, a0.x, c0.x); ffma2(x00, a0.y, c0.y);
            ffma2(x01, a0.x, c1.x); ffma2(x01, a0.y, c1.y);
            ffma2(x10, a1.x, c0.x); ffma2(x10, a1.y, c0.y);
            ffma2(x11, a1.x, c1.x); ffma2(x11, a1.y, c1.y);
            ulonglong2 p0 = hr0[j], p1 = hr1[j], q0 = wh0[j], q1 = wh1[j];
            ffma2(h00, p0.x, q0.x); ffma2(h00, p0.y, q0.y);
            ffma2(h01, p0.x, q1.x); ffma2(h01, p0.y, q1.y);
            ffma2(h10, p1.x, q0.x); ffma2(h10, p1.y, q0.y);
            ffma2(h11, p1.x, q1.x); ffma2(h11, p1.y, q1.y);
        }
        const float* gkb = g_gk + (b * NQ + half * 18) * G3;
        float gxA0 = gkb[i2 * G3 + o2] + hsum2(x00);
        float ghA0 = bhh[o2] + hsum2(h00);
        float gxA1 = gkb[(i2 + 9) * G3 + o2] + hsum2(x10);
        float ghA1 = bhh[o2] + hsum2(h10);
        sumS[i2 * 72 + o2]      = gxA0 + ghA0;
        sumS[(i2 + 9) * 72 + o2] = gxA1 + ghA1;
        int oB = o2 + 54;
        float gxB0 = gkb[i2 * G3 + oB] + hsum2(x01);
        float ghB0 = bhh[oB] + hsum2(h01);
        float gxB1 = gkb[(i2 + 9) * G3 + oB] + hsum2(x11);
        float ghB1 = bhh[oB] + hsum2(h11);
        if (o2 < 18) {
            sumS[i2 * 72 + oB]      = gxB0 + ghB0;
            sumS[(i2 + 9) * 72 + oB] = gxB1 + ghB1;
        } else {
            int on = o2 - 18;
            gxnS[i2 * NQ + on]      = gxB0;
            ghnS[i2 * NQ + on]      = ghB0;
            gxnS[(i2 + 9) * NQ + on] = gxB1;
            ghnS[(i2 + 9) * NQ + on] = ghB1;
        }
    }
    __syncthreads();

    for (int idx = t; idx < 648; idx += 512) {
        int i = idx / NQ, qq = idx - i * NQ;
        float r = 1.f / (1.f + expf(-sumS[i * 72 + qq]));
        float z = 1.f / (1.f + expf(-sumS[i * 72 + 36 + qq]));
        float n = tanhf(gxnS[idx] + r * ghnS[idx]);
        float hp = hpS[idx];
        gnewS[idx] = (1.f - z) * n + z * hp;
    }
    __syncthreads();

    for (int i = wp; i < 18; i += 16) {
        float v1 = (lane < NQ) ? gnewS[i * NQ + lane] : 0.f;
        float v2 = (lane < 4)  ? gnewS[i * NQ + lane + 32] : 0.f;
        float s = v1 + v2;
        for (int o = 16; o; o >>= 1) s += __shfl_xor_sync(~0u, s, o);
        float mu = s * (1.f / 36.f);
        float d1 = (lane < NQ) ? (v1 - mu) : 0.f;
        float d2 = (lane < 4)  ? (v2 - mu) : 0.f;
        float vv = d1 * d1 + d2 * d2;
        for (int o = 16; o; o >>= 1) vv += __shfl_xor_sync(~0u, vv, o);
        float inv = rsqrtf(vv * (1.f / 36.f) + 1e-5f);
        if (lane < NQ) ffS[i * NQ + lane]      = d1 * inv * lnfg[lane] + lnfb[lane];
        if (lane < 4)  ffS[i * NQ + lane + 32] = d2 * inv * lnfg[lane + 32] + lnfb[lane + 32];
    }
    __syncthreads();

    // (b) hidden = relu(ff @ W1^T + b1): thread = h (w1p prefetched)
    {
        for (int i = 0; i < 18; i++) {
            u64 a0 = 0, a1 = 0;
            const ulonglong2* fr = (const ulonglong2*)(ffS + i * NQ);
            #pragma unroll
            for (int c = 0; c < 9; c++) {
                ulonglong2 u = fr[c];
                ffma2(a0, u.x, w1p[c].x);
                ffma2(a1, u.y, w1p[c].y);
            }
            hidS[i * HP + t] = fmaxf(bb1 + hsum2(a0) + hsum2(a1), 0.f);
        }
    }
    __syncthreads();

    for (int q = wp; q < NQ; q += 16) {
        ulonglong2 w2r[4];
        const ulonglong2* wr = (const ulonglong2*)(W2 + q * NH);
        #pragma unroll
        for (int k = 0; k < 4; k++) w2r[k] = wr[lane + 32 * k];
        float bq = b2[q];
        for (int i = 0; i < 18; i++) {
            const ulonglong2* hr = (const ulonglong2*)(hidS + i * HP);
            u64 a0 = 0, a1 = 0;
            #pragma unroll
            for (int k = 0; k < 4; k += 2) {
                ulonglong2 u0 = hr[lane + 32 * k];
                ulonglong2 u1 = hr[lane + 32 * (k + 1)];
                ffma2(a0, u0.x, w2r[k].x);     ffma2(a0, u0.y, w2r[k].y);
                ffma2(a1, u1.x, w2r[k + 1].x); ffma2(a1, u1.y, w2r[k + 1].y);
            }
            float p = hsum2(a0) + hsum2(a1);
            for (int o = 16; o; o >>= 1) p += __shfl_xor_sync(~0u, p, o);
            if (lane == 0)
                slots_out[rbase + i * NQ + q] = gnewS[i * NQ + q] + bq + p;
        }
    }
}

static const int KG_SMEM = KG2_FLOATS * 4;
static const int KP_SMEM = ((NV + 54) * 516 + 162 * 12) * 4;
static const int KGK_SMEM = (G3 + NL) * KNP * 4;

extern "C" void kernel_launch(void* const* d_in, const int* in_sizes, int n_in,
                              void* d_out, int out_size) {
    const float* ctx  = (const float*)d_in[1];
    const float* kn   = (const float*)d_in[4];
    const float* pano = (const float*)d_in[5];
    const float* Wq   = (const float*)d_in[6];
    const float* Wk   = (const float*)d_in[7];
    const float* Wih  = (const float*)d_in[8];
    const float* Whh  = (const float*)d_in[9];
    const float* bih  = (const float*)d_in[10];
    const float* bhh  = (const float*)d_in[11];
    const float* lsg  = (const float*)d_in[12];
    const float* lsb  = (const float*)d_in[13];
    const float* lfg  = (const float*)d_in[14];
    const float* lfb  = (const float*)d_in[15];
    const float* W1   = (const float*)d_in[16];
    const float* b1   = (const float*)d_in[17];
    const float* W2   = (const float*)d_in[18];
    const float* b2   = (const float*)d_in[19];

    float* out = (float*)d_out;
    float* slots = out;                       // [B,36,36]; attn slabs follow

    cudaFuncSetAttribute(k_g, cudaFuncAttributeMaxDynamicSharedMemorySize, KG_SMEM);
    cudaFuncSetAttribute(k_projW, cudaFuncAttributeMaxDynamicSharedMemorySize, KP_SMEM);
    cudaFuncSetAttribute(k_gk, cudaFuncAttributeMaxDynamicSharedMemorySize, KGK_SMEM);

    k_gk<<<NB, 512, KGK_SMEM>>>(kn, Wih, bih);
    k_w<<<NB, 256>>>(pano, 0, lsg, lsb, Wq, Wk);

    for (int it = 0; it < 3; it++) {
        float* attnT = out + NB * NL * NV * (1 + it);
        const float* sp = it ? (const float*)slots : pano;
        int bs = it ? 1296 : 0;
        if (it == 0) {
            k_cd<<<dim3(NV, NB), 128>>>(ctx, attnT);
            k_projW<<<dim3(NB, 2), 384, KP_SMEM>>>(Wih);
        } else {
            k_d2h<<<dim3(NL, NB), 128>>>(attnT);
        }
        k_g<<<dim3(NB, 2), 512, KG_SMEM>>>(attnT, sp, bs, Whh, bhh, lfg, lfb,
                                           W1, b1, W2, b2, it == 0 ? 1 : 0,
                                           attnT, slots);
        if (it < 2)
            k_w<<<NB, 256>>>(slots, 1296, lsg, lsb, Wq, Wk);
    }
}

// round 15
// speedup vs baseline: 1.0309x; 1.0309x over previous
#include <cuda_runtime.h>
#include <cuda_fp16.h>

#define NB 128
#define NL 36
#define NV 36
#define ND 512
#define NKV 112
#define NQ 36
#define NH 512
#define G3 108
#define CKDIM 812   // D + KD
#define XDIM 624    // D + KV
#define HP 516      // padded pitch (conflict-free LDS.128)
#define KNP 116     // padded pitch for knowledge rows

typedef unsigned long long u64;

__device__ __forceinline__ void ffma2(u64& d, u64 a, u64 b) {
    asm("fma.rn.f32x2 %0, %1, %2, %0;" : "+l"(d) : "l"(a), "l"(b));
}
__device__ __forceinline__ float hsum2(u64 v) {
    float lo, hi;
    asm("mov.b64 {%0,%1}, %2;" : "=f"(lo), "=f"(hi) : "l"(v));
    return lo + hi;
}

// ---------------- scratch ----------------
__device__ float g_csum[NB * NV * ND];
__device__ float g_csumWT[NB * G3 * NQ];  // [b][o][v]
__device__ float g_gk[NB * NL * G3];
__device__ float g_w[NB * ND];
__device__ uint2 g_ctxh[NB * NL * NV * (ND / 4)];  // fp16x4-packed context copy (170MB)

// ---------------- gk = knowledge @ Wih_k^T + bih : one block per batch ----------------
__global__ __launch_bounds__(512) void k_gk(const float* __restrict__ kn,
                                            const float* __restrict__ Wih,
                                            const float* __restrict__ bih) {
    extern __shared__ float s[];
    float* wS  = s;                 // G3 x KNP
    float* knS = s + G3 * KNP;      // NL x KNP
    int b = blockIdx.x, t = threadIdx.x;
    for (int i = t; i < G3 * NKV; i += 512) {
        int o = i / NKV, c = i - o * NKV;
        wS[o * KNP + c] = Wih[o * XDIM + ND + c];
    }
    const float* knb = kn + (size_t)b * NL * NKV;
    for (int i = t; i < NL * NKV; i += 512) {
        int l = i / NKV, c = i - l * NKV;
        knS[l * KNP + c] = knb[i];
    }
    __syncthreads();
    for (int idx = t; idx < NL * G3; idx += 512) {
        int l = idx / G3, o = idx - l * G3;
        const ulonglong2* kr = (const ulonglong2*)(knS + l * KNP);
        const ulonglong2* wr = (const ulonglong2*)(wS + o * KNP);
        u64 a0 = 0, a1 = 0;
        #pragma unroll 7
        for (int c = 0; c < 28; c += 2) {
            ulonglong2 u0 = kr[c], w0 = wr[c], u1 = kr[c + 1], w1 = wr[c + 1];
            ffma2(a0, u0.x, w0.x); ffma2(a0, u0.y, w0.y);
            ffma2(a1, u1.x, w1.x); ffma2(a1, u1.y, w1.y);
        }
        g_gk[(size_t)(b * NL + l) * G3 + o] = bih[o] + hsum2(a0) + hsum2(a1);
    }
}

// ---------------- projection vector w (per-iteration) ----------------
__global__ void k_w(const float* __restrict__ slots, int bstride,
                    const float* __restrict__ lng, const float* __restrict__ lnb,
                    const float* __restrict__ Wq, const float* __restrict__ Wk) {
    int b = blockIdx.x;
    int t = threadIdx.x, lane = t & 31, wid = t >> 5;
    __shared__ float lnS[NQ * NQ];
    __shared__ float lnsum[NQ];
    __shared__ float qsum[NQ];
    const float* sp = slots + (size_t)bstride * b;
    for (int i = wid; i < NQ; i += 8) {
        float v1 = (lane < NQ)      ? sp[i * NQ + lane]      : 0.f;
        float v2 = (lane < NQ - 32) ? sp[i * NQ + lane + 32] : 0.f;
        float s = v1 + v2;
        for (int o = 16; o; o >>= 1) s += __shfl_xor_sync(~0u, s, o);
        float mu = s * (1.f / 36.f);
        float d1 = (lane < NQ) ? (v1 - mu) : 0.f;
        float d2 = (lane < NQ - 32) ? (v2 - mu) : 0.f;
        float vv = d1 * d1 + d2 * d2;
        for (int o = 16; o; o >>= 1) vv += __shfl_xor_sync(~0u, vv, o);
        float inv = rsqrtf(vv * (1.f / 36.f) + 1e-5f);
        if (lane < NQ)      lnS[i * NQ + lane]      = d1 * inv * lng[lane] + lnb[lane];
        if (lane < NQ - 32) lnS[i * NQ + lane + 32] = d2 * inv * lng[lane + 32] + lnb[lane + 32];
    }
    __syncthreads();
    if (t < NQ) {
        float s = 0.f;
        for (int i = 0; i < NQ; i++) s += lnS[i * NQ + t];
        lnsum[t] = s;
    }
    __syncthreads();
    if (t < NQ) {
        float s = 0.f;
        #pragma unroll 4
        for (int e = 0; e < NQ; e++) s += lnsum[e] * Wq[t * NQ + e];
        qsum[t] = s;
    }
    __syncthreads();
    for (int c = t; c < ND; c += blockDim.x) {
        float s = 0.f;
        #pragma unroll 4
        for (int d = 0; d < NQ; d++) s += qsum[d] * Wk[d * CKDIM + c];
        g_w[b * ND + c] = s * (1.f / 6.f);
    }
}

// ---------------- fused iter-0: csum + dots + fp16 context copy ----------------
__global__ __launch_bounds__(128) void k_cd(const float* __restrict__ ctx,
                                            float* __restrict__ dots0) {
    int v = blockIdx.x, b = blockIdx.y;
    int t = threadIdx.x, lane = t & 31, w = t >> 5;
    __shared__ float ppS[18 * 129];
    const float4* wb = (const float4*)(g_w + b * ND);
    float4 w4 = wb[t];
    float4 acc = {0.f, 0.f, 0.f, 0.f};
    size_t row0 = (size_t)b * NL * NV + v;
    const float4* base = (const float4*)ctx + row0 * (ND / 4) + t;
    #pragma unroll 1
    for (int half = 0; half < 2; half++) {
        #pragma unroll 3
        for (int li = 0; li < 18; li++) {
            int l = half * 18 + li;
            float4 c = base[(size_t)l * NV * (ND / 4)];
            acc.x += c.x; acc.y += c.y; acc.z += c.z; acc.w += c.w;
            ppS[li * 129 + t] = c.x * w4.x + c.y * w4.y + c.z * w4.z + c.w * w4.w;
            __half2 h0 = __floats2half2_rn(c.x, c.y);
            __half2 h1 = __floats2half2_rn(c.z, c.w);
            uint2 u;
            u.x = *(unsigned*)&h0;
            u.y = *(unsigned*)&h1;
            g_ctxh[(row0 + (size_t)l * NV) * (ND / 4) + t] = u;
        }
        __syncthreads();
        for (int li = w; li < 18; li += 4) {
            float s = ppS[li * 129 + lane] + ppS[li * 129 + lane + 32]
                    + ppS[li * 129 + lane + 64] + ppS[li * 129 + lane + 96];
            for (int o = 16; o; o >>= 1) s += __shfl_xor_sync(~0u, s, o);
            if (lane == 0) dots0[(b * NL + half * 18 + li) * NV + v] = s;
        }
        __syncthreads();
    }
    ((float4*)g_csum)[(b * NV + v) * (ND / 4) + t] = acc;
}

// ---------------- projection: csumWT[b] = Wihu @ csum[b]^T ----------------
// One block per batch (grid=128 -> single wave). Only csum staged in smem
// (74KB); Wihu rows read via LDG (L2/L1-resident, batch-invariant).
// 324 workers: 3(o)x4(v) register tiles. 512 threads = 16 warps.
__global__ __launch_bounds__(512) void k_projW(const float* __restrict__ Wih) {
    int b = blockIdx.x;
    int t = threadIdx.x;
    extern __shared__ float sm[];
    float* csS = sm;                 // 36 rows, pitch 516
    const float4* src = (const float4*)(g_csum + (size_t)b * NV * ND);
    for (int i = t; i < NV * 128; i += 512) {
        int v = i >> 7, c4 = i & 127;
        ((float4*)(csS + v * 516))[c4] = src[i];
    }
    __syncthreads();
    if (t < 324) {
        int ot = t / 9, vt = t - (t / 9) * 9;   // ot 0..35, vt 0..8
        const ulonglong2* w0 = (const ulonglong2*)(Wih + (size_t)ot * XDIM);
        const ulonglong2* w1 = (const ulonglong2*)(Wih + (size_t)(ot + 36) * XDIM);
        const ulonglong2* w2 = (const ulonglong2*)(Wih + (size_t)(ot + 72) * XDIM);
        const ulonglong2* c0 = (const ulonglong2*)(csS + vt * 516);
        const ulonglong2* c1 = (const ulonglong2*)(csS + (vt + 9) * 516);
        const ulonglong2* c2 = (const ulonglong2*)(csS + (vt + 18) * 516);
        const ulonglong2* c3 = (const ulonglong2*)(csS + (vt + 27) * 516);
        u64 acc[12];
        #pragma unroll
        for (int i = 0; i < 12; i++) acc[i] = 0;
        #pragma unroll 4
        for (int c = 0; c < 128; c++) {
            ulonglong2 a0 = w0[c], a1 = w1[c], a2 = w2[c];
            ulonglong2 b0 = c0[c], b1 = c1[c], b2 = c2[c], b3 = c3[c];
            ffma2(acc[0],  b0.x, a0.x); ffma2(acc[0],  b0.y, a0.y);
            ffma2(acc[1],  b1.x, a0.x); ffma2(acc[1],  b1.y, a0.y);
            ffma2(acc[2],  b2.x, a0.x); ffma2(acc[2],  b2.y, a0.y);
            ffma2(acc[3],  b3.x, a0.x); ffma2(acc[3],  b3.y, a0.y);
            ffma2(acc[4],  b0.x, a1.x); ffma2(acc[4],  b0.y, a1.y);
            ffma2(acc[5],  b1.x, a1.x); ffma2(acc[5],  b1.y, a1.y);
            ffma2(acc[6],  b2.x, a1.x); ffma2(acc[6],  b2.y, a1.y);
            ffma2(acc[7],  b3.x, a1.x); ffma2(acc[7],  b3.y, a1.y);
            ffma2(acc[8],  b0.x, a2.x); ffma2(acc[8],  b0.y, a2.y);
            ffma2(acc[9],  b1.x, a2.x); ffma2(acc[9],  b1.y, a2.y);
            ffma2(acc[10], b2.x, a2.x); ffma2(acc[10], b2.y, a2.y);
            ffma2(acc[11], b3.x, a2.x); ffma2(acc[11], b3.y, a2.y);
        }
        float* outb = g_csumWT + b * G3 * NQ;
        #pragma unroll
        for (int oi = 0; oi < 3; oi++)
            #pragma unroll
            for (int vi = 0; vi < 4; vi++)
                outb[(ot + oi * 36) * NQ + (vt + vi * 9)] = hsum2(acc[oi * 4 + vi]);
    }
}

// ---------------- iters 1,2: streaming dots + softmax over fp16 context ----------------
__global__ __launch_bounds__(128) void k_d2h(float* __restrict__ attnT) {
    int l = blockIdx.x, b = blockIdx.y;
    int t = threadIdx.x, lane = t & 31, w = t >> 5;
    __shared__ float ppS[18 * 129];
    __shared__ float dotsS[NV];
    const float4* wb = (const float4*)(g_w + b * ND);
    float4 w4 = wb[t];
    const uint2* base = g_ctxh + ((size_t)(b * NL + l) * NV) * (ND / 4) + t;
    #pragma unroll 1
    for (int half = 0; half < 2; half++) {
        #pragma unroll 3
        for (int vi = 0; vi < 18; vi++) {
            int v = half * 18 + vi;
            uint2 u = base[v * (ND / 4)];
            float2 f0 = __half22float2(*(__half2*)&u.x);
            float2 f1 = __half22float2(*(__half2*)&u.y);
            ppS[vi * 129 + t] = f0.x * w4.x + f0.y * w4.y + f1.x * w4.z + f1.y * w4.w;
        }
        __syncthreads();
        for (int vi = w; vi < 18; vi += 4) {
            float s = ppS[vi * 129 + lane] + ppS[vi * 129 + lane + 32]
                    + ppS[vi * 129 + lane + 64] + ppS[vi * 129 + lane + 96];
            for (int o = 16; o; o >>= 1) s += __shfl_xor_sync(~0u, s, o);
            if (lane == 0) dotsS[half * 18 + vi] = s;
        }
        __syncthreads();
    }
    if (w == 0) {
        float x1 = dotsS[lane];
        float x2 = (lane < 4) ? dotsS[lane + 32] : -1e30f;
        float m = fmaxf(x1, x2);
        for (int o = 16; o; o >>= 1) m = fmaxf(m, __shfl_xor_sync(~0u, m, o));
        float e1 = expf(x1 - m);
        float e2 = (lane < 4) ? expf(x2 - m) : 0.f;
        float s = e1 + e2;
        for (int o = 16; o; o >>= 1) s += __shfl_xor_sync(~0u, s, o);
        float inv = 1.f / s;
        float* arow = attnT + (b * NL + l) * NV;
        arow[lane] = e1 * inv;
        if (lane < 4) arow[lane + 32] = e2 * inv;
    }
}

// ---------------- fused GRU + LN + MLP, split per (b, i-half). 53KB smem. ----------------
#define KG2_FLOATS 13176
__global__ __launch_bounds__(512) void k_g(const float* __restrict__ attnT,
                                           const float* __restrict__ slots_prev, int bstride,
                                           const float* __restrict__ Whh,
                                           const float* __restrict__ bhh,
                                           const float* __restrict__ lnfg, const float* __restrict__ lnfb,
                                           const float* __restrict__ W1, const float* __restrict__ b1,
                                           const float* __restrict__ W2, const float* __restrict__ b2,
                                           int do_sm,
                                           float* __restrict__ attnT_out,
                                           float* __restrict__ slots_out) {
    extern __shared__ float sm[];
    float* attnS = sm;            // -> gnewS
    float* hpS   = sm + 648;      // -> ffS
    float* sumS  = sm + 1296;
    float* gxnS  = sm + 2592;
    float* ghnS  = sm + 3240;
    float* hidS  = sm + 3888;
    float* gnewS = attnS;
    float* ffS   = hpS;
    int b = blockIdx.x, half = blockIdx.y;
    int t = threadIdx.x, lane = t & 31, wp = t >> 5;
    int rbase = b * 1296 + half * 648;

    // hoisted independent W1-row prefetch (overlaps smem-fill latency)
    ulonglong2 w1p[9];
    {
        const ulonglong2* wr = (const ulonglong2*)(W1 + t * NQ);
        #pragma unroll
        for (int c = 0; c < 9; c++) w1p[c] = wr[c];
    }
    float bb1 = b1[t];

    for (int i = t; i < 648; i += 512) {
        attnS[i] = attnT[rbase + i];
        hpS[i] = slots_prev[(size_t)bstride * b + half * 648 + i];
    }
    __syncthreads();

    if (do_sm) {
        for (int i = wp; i < 18; i += 16) {
            float x1 = (lane < NV) ? attnS[i * NV + lane] : -1e30f;
            float x2 = (lane < 4)  ? attnS[i * NV + lane + 32] : -1e30f;
            float m = fmaxf(x1, x2);
            for (int o = 16; o; o >>= 1) m = fmaxf(m, __shfl_xor_sync(~0u, m, o));
            float e1 = (lane < NV) ? expf(x1 - m) : 0.f;
            float e2 = (lane < 4)  ? expf(x2 - m) : 0.f;
            float s = e1 + e2;
            for (int o = 16; o; o >>= 1) s += __shfl_xor_sync(~0u, s, o);
            float inv = 1.f / s;
            float* arow = attnT_out + rbase + i * NV;
            if (lane < NV) { attnS[i * NV + lane] = e1 * inv; arow[lane] = e1 * inv; }
            if (lane < 4)  { attnS[i * NV + lane + 32] = e2 * inv; arow[lane + 32] = e2 * inv; }
        }
        __syncthreads();
    }

    // (a) gates: 2x2 tiles (i2,i2+9) x (o2,o2+54), 486 tasks
    if (t < 486) {
        int i2 = t / 54, o2 = t - i2 * 54;
        const ulonglong2* ar0 = (const ulonglong2*)(attnS + i2 * NQ);
        const ulonglong2* ar1 = (const ulonglong2*)(attnS + (i2 + 9) * NQ);
        const ulonglong2* hr0 = (const ulonglong2*)(hpS + i2 * NQ);
        const ulonglong2* hr1 = (const ulonglong2*)(hpS + (i2 + 9) * NQ);
        const ulonglong2* cw0 = (const ulonglong2*)(g_csumWT + b * G3 * NQ + o2 * NQ);
        const ulonglong2* cw1 = (const ulonglong2*)(g_csumWT + b * G3 * NQ + (o2 + 54) * NQ);
        const ulonglong2* wh0 = (const ulonglong2*)(Whh + o2 * NQ);
        const ulonglong2* wh1 = (const ulonglong2*)(Whh + (o2 + 54) * NQ);
        u64 x00 = 0, x01 = 0, x10 = 0, x11 = 0;
        u64 h00 = 0, h01 = 0, h10 = 0, h11 = 0;
        #pragma unroll
        for (int j = 0; j < 9; j++) {
            ulonglong2 a0 = ar0[j], a1 = ar1[j], c0 = cw0[j], c1 = cw1[j];
            ffma2(x00, a0.x, c0.x); ffma2(x00, a0.y, c0.y);
            ffma2(x01, a0.x, c1.x); ffma2(x01, a0.y, c1.y);
            ffma2(x10, a1.x, c0.x); ffma2(x10, a1.y, c0.y);
            ffma2(x11, a1.x, c1.x); ffma2(x11, a1.y, c1.y);
            ulonglong2 p0 = hr0[j], p1 = hr1[j], q0 = wh0[j], q1 = wh1[j];
            ffma2(h00, p0.x, q0.x); ffma2(h00, p0.y, q0.y);
            ffma2(h01, p0.x, q1.x); ffma2(h01, p0.y, q1.y);
            ffma2(h10, p1.x, q0.x); ffma2(h10, p1.y, q0.y);
            ffma2(h11, p1.x, q1.x); ffma2(h11, p1.y, q1.y);
        }
        const float* gkb = g_gk + (b * NQ + half * 18) * G3;
        float gxA0 = gkb[i2 * G3 + o2] + hsum2(x00);
        float ghA0 = bhh[o2] + hsum2(h00);
        float gxA1 = gkb[(i2 + 9) * G3 + o2] + hsum2(x10);
        float ghA1 = bhh[o2] + hsum2(h10);
        sumS[i2 * 72 + o2]      = gxA0 + ghA0;
        sumS[(i2 + 9) * 72 + o2] = gxA1 + ghA1;
        int oB = o2 + 54;
        float gxB0 = gkb[i2 * G3 + oB] + hsum2(x01);
        float ghB0 = bhh[oB] + hsum2(h01);
        float gxB1 = gkb[(i2 + 9) * G3 + oB] + hsum2(x11);
        float ghB1 = bhh[oB] + hsum2(h11);
        if (o2 < 18) {
            sumS[i2 * 72 + oB]      = gxB0 + ghB0;
            sumS[(i2 + 9) * 72 + oB] = gxB1 + ghB1;
        } else {
            int on = o2 - 18;
            gxnS[i2 * NQ + on]      = gxB0;
            ghnS[i2 * NQ + on]      = ghB0;
            gxnS[(i2 + 9) * NQ + on] = gxB1;
            ghnS[(i2 + 9) * NQ + on] = ghB1;
        }
    }
    __syncthreads();

    for (int idx = t; idx < 648; idx += 512) {
        int i = idx / NQ, qq = idx - i * NQ;
        float r = 1.f / (1.f + expf(-sumS[i * 72 + qq]));
        float z = 1.f / (1.f + expf(-sumS[i * 72 + 36 + qq]));
        float n = tanhf(gxnS[idx] + r * ghnS[idx]);
        float hp = hpS[idx];
        gnewS[idx] = (1.f - z) * n + z * hp;
    }
    __syncthreads();

    for (int i = wp; i < 18; i += 16) {
        float v1 = (lane < NQ) ? gnewS[i * NQ + lane] : 0.f;
        float v2 = (lane < 4)  ? gnewS[i * NQ + lane + 32] : 0.f;
        float s = v1 + v2;
        for (int o = 16; o; o >>= 1) s += __shfl_xor_sync(~0u, s, o);
        float mu = s * (1.f / 36.f);
        float d1 = (lane < NQ) ? (v1 - mu) : 0.f;
        float d2 = (lane < 4)  ? (v2 - mu) : 0.f;
        float vv = d1 * d1 + d2 * d2;
        for (int o = 16; o; o >>= 1) vv += __shfl_xor_sync(~0u, vv, o);
        float inv = rsqrtf(vv * (1.f / 36.f) + 1e-5f);
        if (lane < NQ) ffS[i * NQ + lane]      = d1 * inv * lnfg[lane] + lnfb[lane];
        if (lane < 4)  ffS[i * NQ + lane + 32] = d2 * inv * lnfg[lane + 32] + lnfb[lane + 32];
    }
    __syncthreads();

    // (b) hidden = relu(ff @ W1^T + b1): thread = h (w1p prefetched)
    {
        for (int i = 0; i < 18; i++) {
            u64 a0 = 0, a1 = 0;
            const ulonglong2* fr = (const ulonglong2*)(ffS + i * NQ);
            #pragma unroll
            for (int c = 0; c < 9; c++) {
                ulonglong2 u = fr[c];
                ffma2(a0, u.x, w1p[c].x);
                ffma2(a1, u.y, w1p[c].y);
            }
            hidS[i * HP + t] = fmaxf(bb1 + hsum2(a0) + hsum2(a1), 0.f);
        }
    }
    __syncthreads();

    for (int q = wp; q < NQ; q += 16) {
        ulonglong2 w2r[4];
        const ulonglong2* wr = (const ulonglong2*)(W2 + q * NH);
        #pragma unroll
        for (int k = 0; k < 4; k++) w2r[k] = wr[lane + 32 * k];
        float bq = b2[q];
        for (int i = 0; i < 18; i++) {
            const ulonglong2* hr = (const ulonglong2*)(hidS + i * HP);
            u64 a0 = 0, a1 = 0;
            #pragma unroll
            for (int k = 0; k < 4; k += 2) {
                ulonglong2 u0 = hr[lane + 32 * k];
                ulonglong2 u1 = hr[lane + 32 * (k + 1)];
                ffma2(a0, u0.x, w2r[k].x);     ffma2(a0, u0.y, w2r[k].y);
                ffma2(a1, u1.x, w2r[k + 1].x); ffma2(a1, u1.y, w2r[k + 1].y);
            }
            float p = hsum2(a0) + hsum2(a1);
            for (int o = 16; o; o >>= 1) p += __shfl_xor_sync(~0u, p, o);
            if (lane == 0)
                slots_out[rbase + i * NQ + q] = gnewS[i * NQ + q] + bq + p;
        }
    }
}

static const int KG_SMEM = KG2_FLOATS * 4;
static const int KP_SMEM = NV * 516 * 4;
static const int KGK_SMEM = (G3 + NL) * KNP * 4;

extern "C" void kernel_launch(void* const* d_in, const int* in_sizes, int n_in,
                              void* d_out, int out_size) {
    const float* ctx  = (const float*)d_in[1];
    const float* kn   = (const float*)d_in[4];
    const float* pano = (const float*)d_in[5];
    const float* Wq   = (const float*)d_in[6];
    const float* Wk   = (const float*)d_in[7];
    const float* Wih  = (const float*)d_in[8];
    const float* Whh  = (const float*)d_in[9];
    const float* bih  = (const float*)d_in[10];
    const float* bhh  = (const float*)d_in[11];
    const float* lsg  = (const float*)d_in[12];
    const float* lsb  = (const float*)d_in[13];
    const float* lfg  = (const float*)d_in[14];
    const float* lfb  = (const float*)d_in[15];
    const float* W1   = (const float*)d_in[16];
    const float* b1   = (const float*)d_in[17];
    const float* W2   = (const float*)d_in[18];
    const float* b2   = (const float*)d_in[19];

    float* out = (float*)d_out;
    float* slots = out;                       // [B,36,36]; attn slabs follow

    cudaFuncSetAttribute(k_g, cudaFuncAttributeMaxDynamicSharedMemorySize, KG_SMEM);
    cudaFuncSetAttribute(k_projW, cudaFuncAttributeMaxDynamicSharedMemorySize, KP_SMEM);
    cudaFuncSetAttribute(k_gk, cudaFuncAttributeMaxDynamicSharedMemorySize, KGK_SMEM);

    k_gk<<<NB, 512, KGK_SMEM>>>(kn, Wih, bih);
    k_w<<<NB, 256>>>(pano, 0, lsg, lsb, Wq, Wk);

    for (int it = 0; it < 3; it++) {
        float* attnT = out + NB * NL * NV * (1 + it);
        const float* sp = it ? (const float*)slots : pano;
        int bs = it ? 1296 : 0;
        if (it == 0) {
            k_cd<<<dim3(NV, NB), 128>>>(ctx, attnT);
            k_projW<<<NB, 512, KP_SMEM>>>(Wih);
        } else {
            k_d2h<<<dim3(NL, NB), 128>>>(attnT);
        }
        k_g<<<dim3(NB, 2), 512, KG_SMEM>>>(attnT, sp, bs, Whh, bhh, lfg, lfb,
                                           W1, b1, W2, b2, it == 0 ? 1 : 0,
                                           attnT, slots);
        if (it < 2)
            k_w<<<NB, 256>>>(slots, 1296, lsg, lsb, Wq, Wk);
    }
}